// round 1
// baseline (speedup 1.0000x reference)
#include <cuda_runtime.h>
#include <cstdint>

// Problem constants
#define M_TOTAL 32768      // B*L = 64*512 tokens
#define K_DIM   1536       // H2
#define T_DIM   64         // tags
#define BLOCK_M 256        // tokens per block
#define KB      16         // K-tile depth
#define NT      (K_DIM / KB)        // 96 K-tiles
#define NBLOCKS (M_TOTAL / BLOCK_M) // 128 blocks
#define XS_STRIDE 260      // padded row stride for transposed x tile (multiple of 4)

// Deterministic two-stage reduction scratch
__device__ float g_part_loss[NBLOCKS];
__device__ int   g_part_right[NBLOCKS];
__device__ int   g_part_valid[NBLOCKS];
__device__ int   g_tag_stride;   // 1 = int32 tags, 2 = int64 tags

// ---------------------------------------------------------------------------
// Packed fp32x2 helpers (Blackwell FFMA2 — PTX-only, 2x fp32 FMA throughput)
// ---------------------------------------------------------------------------
__device__ __forceinline__ unsigned long long dupf(float a) {
    unsigned long long r;
    asm("mov.b64 %0, {%1, %1};" : "=l"(r) : "f"(a));
    return r;
}
__device__ __forceinline__ void fma2(unsigned long long& d,
                                     unsigned long long a,
                                     unsigned long long b) {
    asm("fma.rn.f32x2 %0, %1, %2, %0;" : "+l"(d) : "l"(a), "l"(b));
}

// ---------------------------------------------------------------------------
// Detect whether tags are int64 (every odd 32-bit word of the first 128
// elements is zero) or int32. Values are in [0, 64) so this is unambiguous.
// ---------------------------------------------------------------------------
__global__ void detect_tag_stride_kernel(const int* __restrict__ tagw) {
    if (threadIdx.x == 0) {
        int stride = 2;
        for (int i = 0; i < 128; i++) {
            if (tagw[2 * i + 1] != 0) { stride = 1; break; }
        }
        g_tag_stride = stride;
    }
}

// ---------------------------------------------------------------------------
// Tile loaders (global -> regs -> smem), register-prefetched double buffering
// ---------------------------------------------------------------------------
__device__ __forceinline__ void load_tile(const float* __restrict__ x,
                                          const float* __restrict__ W,
                                          int m0, int kt, int tid,
                                          float4 xr[4], float4& wr) {
    const int k0 = kt * KB;
#pragma unroll
    for (int i = 0; i < 4; i++) {
        int idx = tid + i * 256;          // 0..1023 float4 slots
        int m   = idx >> 2;               // token row within tile
        int kc  = idx & 3;                // 4-float chunk within KB
        xr[i] = *(const float4*)(x + (size_t)(m0 + m) * K_DIM + k0 + kc * 4);
    }
    wr = *(const float4*)(W + (size_t)(k0 + (tid >> 4)) * T_DIM + ((tid & 15) << 2));
}

__device__ __forceinline__ void store_tile(float* xs, float (*ws)[T_DIM],
                                           int tid, const float4 xr[4],
                                           const float4& wr) {
#pragma unroll
    for (int i = 0; i < 4; i++) {
        int idx = tid + i * 256;
        int m   = idx >> 2;
        int kc  = idx & 3;
        xs[(kc * 4 + 0) * XS_STRIDE + m] = xr[i].x;
        xs[(kc * 4 + 1) * XS_STRIDE + m] = xr[i].y;
        xs[(kc * 4 + 2) * XS_STRIDE + m] = xr[i].z;
        xs[(kc * 4 + 3) * XS_STRIDE + m] = xr[i].w;
    }
    *(float4*)&ws[tid >> 4][(tid & 15) << 2] = wr;
}

// ---------------------------------------------------------------------------
// Fused kernel: GEMM (fp32 via f32x2) + softmax stats + loss/acc per token
// ---------------------------------------------------------------------------
__global__ __launch_bounds__(256, 1)
void fused_gemm_loss_kernel(const float* __restrict__ x,
                            const float* __restrict__ W,
                            const float* __restrict__ bias,
                            const int*   __restrict__ tagw,   // raw 32-bit view of tags
                            const float* __restrict__ tts,    // tag_to_score [64]
                            const int*   __restrict__ tptr)   // exponent t
{
    __shared__ float xs[KB * XS_STRIDE];   // transposed x tile: xs[k][m]
    __shared__ float ws[KB][T_DIM];        // W tile: ws[k][t]
    __shared__ float s_wloss[8];
    __shared__ int   s_wright[8];
    __shared__ int   s_wvalid[8];

    const int tid = threadIdx.x;
    const int tx  = tid & 7;      // tag-column group: cols tx*8 .. tx*8+7
    const int ty  = tid >> 3;     // token-row group:  rows ty*8 .. ty*8+7
    const int m0  = blockIdx.x * BLOCK_M;

    unsigned long long acc[8][4];
#pragma unroll
    for (int r = 0; r < 8; r++)
#pragma unroll
        for (int c = 0; c < 4; c++) acc[r][c] = 0ULL;

    // ---- main GEMM loop with register prefetch ----
    float4 xr[4]; float4 wr;
    load_tile(x, W, m0, 0, tid, xr, wr);
    store_tile(xs, ws, tid, xr, wr);
    __syncthreads();

    for (int kt = 0; kt < NT; kt++) {
        float4 nxr[4]; float4 nwr;
        const bool has_next = (kt + 1 < NT);
        if (has_next) load_tile(x, W, m0, kt + 1, tid, nxr, nwr);

#pragma unroll
        for (int k = 0; k < KB; k++) {
            const float* xrow = &xs[k * XS_STRIDE + (ty << 3)];
            float4 a0 = *(const float4*)(xrow);
            float4 a1 = *(const float4*)(xrow + 4);
            const float* wcol = &ws[k][tx << 3];
            ulonglong2 b01 = *(const ulonglong2*)(wcol);
            ulonglong2 b23 = *(const ulonglong2*)(wcol + 4);
            float a[8] = {a0.x, a0.y, a0.z, a0.w, a1.x, a1.y, a1.z, a1.w};
#pragma unroll
            for (int r = 0; r < 8; r++) {
                unsigned long long aa = dupf(a[r]);
                fma2(acc[r][0], aa, b01.x);
                fma2(acc[r][1], aa, b01.y);
                fma2(acc[r][2], aa, b23.x);
                fma2(acc[r][3], aa, b23.y);
            }
        }
        __syncthreads();
        if (has_next) {
            store_tile(xs, ws, tid, nxr, nwr);
            __syncthreads();
        }
    }

    // ---- fused epilogue: per-row softmax stats via 8-lane shfl groups ----
    // Read scalar t robustly (int32/int64 first word = 2; fp32 fallback)
    int   traw = *tptr;
    float tf   = (traw > -1000000 && traw < 1000000) ? (float)traw
                                                     : __int_as_float(traw);
    const int tag_stride = g_tag_stride;
    const float E1 = 2.718281828459045f;

    float bcol[8];
#pragma unroll
    for (int c = 0; c < 8; c++) bcol[c] = bias[(tx << 3) + c];

    float thr_loss = 0.0f;
    int   thr_right = 0, thr_valid = 0;

#pragma unroll
    for (int r = 0; r < 8; r++) {
        float v[8];
#pragma unroll
        for (int cp = 0; cp < 4; cp++) {
            v[2 * cp]     = __uint_as_float((unsigned)(acc[r][cp])) + bcol[2 * cp];
            v[2 * cp + 1] = __uint_as_float((unsigned)(acc[r][cp] >> 32)) + bcol[2 * cp + 1];
        }
        const int token = m0 + (ty << 3) + r;
        const int tag   = (tag_stride == 2) ? tagw[2 * token] : tagw[token];

        // local argmax (first occurrence wins on ties)
        float mv = v[0]; int mi = (tx << 3);
#pragma unroll
        for (int c = 1; c < 8; c++) {
            if (v[c] > mv) { mv = v[c]; mi = (tx << 3) + c; }
        }
        // 8-lane group argmax (jnp.argmax tie-break: smallest index)
#pragma unroll
        for (int off = 1; off < 8; off <<= 1) {
            float ov = __shfl_xor_sync(0xffffffffu, mv, off);
            int   oi = __shfl_xor_sync(0xffffffffu, mi, off);
            if (ov > mv || (ov == mv && oi < mi)) { mv = ov; mi = oi; }
        }
        // sums: exp, logits, logit_at_tag
        float se = 0.0f, sl = 0.0f, st = 0.0f;
#pragma unroll
        for (int c = 0; c < 8; c++) {
            se += expf(v[c] - mv);
            sl += v[c];
            if (((tx << 3) + c) == tag) st = v[c];
        }
#pragma unroll
        for (int off = 1; off < 8; off <<= 1) {
            se += __shfl_xor_sync(0xffffffffu, se, off);
            sl += __shfl_xor_sync(0xffffffffu, sl, off);
            st += __shfl_xor_sync(0xffffffffu, st, off);
        }

        if (tx == 0) {
            float LSE = mv + logf(se);
            float s   = powf(tts[tag], tf);
            float es  = expf(s);
            float Z   = 63.0f * E1 + es;
            // loss = LSE - sum_t y_t * logit_t  (y = softmax of ones w/ score at tag)
            float loss = LSE - ((E1 / Z) * (sl - st) + (es / Z) * st);
            thr_loss += loss;
            int valid = (tag < (T_DIM - 3)) ? 1 : 0;
            thr_valid += valid;
            thr_right += (valid && (mi == tag)) ? 1 : 0;
        }
    }

    // ---- deterministic block reduction ----
    const int lane = tid & 31;
    const int warp = tid >> 5;
#pragma unroll
    for (int off = 16; off > 0; off >>= 1) {
        thr_loss  += __shfl_xor_sync(0xffffffffu, thr_loss,  off);
        thr_right += __shfl_xor_sync(0xffffffffu, thr_right, off);
        thr_valid += __shfl_xor_sync(0xffffffffu, thr_valid, off);
    }
    if (lane == 0) {
        s_wloss[warp]  = thr_loss;
        s_wright[warp] = thr_right;
        s_wvalid[warp] = thr_valid;
    }
    __syncthreads();
    if (tid == 0) {
        float L = 0.0f; int R = 0, V = 0;
        for (int w = 0; w < 8; w++) { L += s_wloss[w]; R += s_wright[w]; V += s_wvalid[w]; }
        g_part_loss[blockIdx.x]  = L;
        g_part_right[blockIdx.x] = R;
        g_part_valid[blockIdx.x] = V;
    }
}

// ---------------------------------------------------------------------------
// Final deterministic reduction -> out[0] = loss1, out[1] = acc1
// ---------------------------------------------------------------------------
__global__ void finalize_kernel(float* __restrict__ out) {
    if (threadIdx.x == 0) {
        double L = 0.0; long long R = 0, V = 0;
        for (int i = 0; i < NBLOCKS; i++) {
            L += (double)g_part_loss[i];
            R += (long long)g_part_right[i];
            V += (long long)g_part_valid[i];
        }
        out[0] = (float)L;
        out[1] = (float)((double)R / (double)V);
    }
}

extern "C" void kernel_launch(void* const* d_in, const int* in_sizes, int n_in,
                              void* d_out, int out_size) {
    const float* x    = (const float*)d_in[0];
    const float* W    = (const float*)d_in[1];
    const float* b    = (const float*)d_in[2];
    const int*   tagw = (const int*)d_in[3];   // raw 32-bit view (dtype detected on device)
    // d_in[4] = attention_mask: mathematically a no-op (uniform shift over tag dim)
    const float* tts  = (const float*)d_in[5];
    const int*   tptr = (const int*)d_in[6];

    detect_tag_stride_kernel<<<1, 32>>>(tagw);
    fused_gemm_loss_kernel<<<NBLOCKS, 256>>>(x, W, b, tagw, tts, tptr);
    finalize_kernel<<<1, 32>>>((float*)d_out);
}

// round 4
// speedup vs baseline: 2.1791x; 2.1791x over previous
#include <cuda_runtime.h>
#include <cstdint>

// ---------------- problem constants ----------------
#define M_TOTAL 32768          // B*L tokens
#define K_DIM   1536           // H2
#define T_DIM   64             // tags
#define BM      256            // tokens per CTA
#define BK      32             // K per tile
#define NTK     (K_DIM / BK)   // 48 k-tiles
#define GRID    (M_TOTAL / BM) // 128 CTAs (one wave)
#define THREADS 512            // 16 warps: 4 (m) x 2 (n)

// ---------------- dynamic SMEM layout (bytes) ----------------
// A tiles: [256 rows][32 bf16 = 64B data, padded to 80B], double buffered, hi+lo
// W tiles: [64 rows ][32 bf16 = 64B data, padded to 80B], double buffered, hi+lo
#define SM_REDF   128                    // 16 floats
#define SM_REDR   256                    // 16 ints
#define SM_REDV   320                    // 16 ints
#define SM_BIAS   512                    // 64 floats
#define A_ROW     80
#define A_BUF     (BM * A_ROW)           // 20480
#define W_BUF     (T_DIM * A_ROW)        // 5120
#define A_HI_OFF  1024
#define A_LO_OFF  (A_HI_OFF + 2 * A_BUF) // 41984
#define W_HI_OFF  (A_LO_OFF + 2 * A_BUF) // 82944
#define W_LO_OFF  (W_HI_OFF + 2 * W_BUF) // 93184
#define SMEM_TOTAL (W_LO_OFF + 2 * W_BUF) // 103424
// C overlay (after GEMM): [256][65] f32 at offset 1024 = 66560 bytes (fits)

// ---------------- device scratch (no allocs allowed) ----------------
__device__ float    g_part_loss[GRID];
__device__ int      g_part_right[GRID];
__device__ int      g_part_valid[GRID];
__device__ int      g_tag_stride;
__device__ unsigned g_whi[NTK * 1024];   // W bf16 hi tiles, [kt][n=64][k=32] (uint = 2 bf16)
__device__ unsigned g_wlo[NTK * 1024];   // W bf16 lo tiles

// ---------------- helpers ----------------
__device__ __forceinline__ uint32_t smem_u32(const void* p) {
    uint32_t a;
    asm("{ .reg .u64 t; cvta.to.shared.u64 t, %1; cvt.u32.u64 %0, t; }" : "=r"(a) : "l"(p));
    return a;
}
__device__ __forceinline__ unsigned cvt_bf16x2(float a, float b) {
    // result: lo16 = bf16(a), hi16 = bf16(b)
    unsigned r;
    asm("cvt.rn.bf16x2.f32 %0, %1, %2;" : "=r"(r) : "f"(b), "f"(a));
    return r;
}
__device__ __forceinline__ float lo_f32(unsigned w) { return __uint_as_float(w << 16); }
__device__ __forceinline__ float hi_f32(unsigned w) { return __uint_as_float(w & 0xffff0000u); }

#define LDMX4(r, addr)                                                          \
    asm volatile("ldmatrix.sync.aligned.m8n8.x4.shared.b16 {%0,%1,%2,%3}, [%4];"\
                 : "=r"((r)[0]), "=r"((r)[1]), "=r"((r)[2]), "=r"((r)[3])       \
                 : "r"(addr))

#define MMA16816(c, a, b0, b1)                                                  \
    asm volatile("mma.sync.aligned.m16n8k16.row.col.f32.bf16.bf16.f32 "         \
                 "{%0,%1,%2,%3}, {%4,%5,%6,%7}, {%8,%9}, {%0,%1,%2,%3};"        \
                 : "+f"((c)[0]), "+f"((c)[1]), "+f"((c)[2]), "+f"((c)[3])       \
                 : "r"((a)[0]), "r"((a)[1]), "r"((a)[2]), "r"((a)[3]),          \
                   "r"(b0), "r"(b1))

// ---------------- tag dtype detection (int32 vs int64) ----------------
__global__ void detect_tag_stride_kernel(const int* __restrict__ tagw) {
    if (threadIdx.x == 0) {
        int stride = 2;
        for (int i = 0; i < 128; i++)
            if (tagw[2 * i + 1] != 0) { stride = 1; break; }
        g_tag_stride = stride;
    }
}

// ---------------- W -> bf16 hi/lo [kt][n][k] tiles ----------------
__global__ void w_convert_kernel(const float* __restrict__ W) {
    const int kt  = blockIdx.x;
    const int t   = threadIdx.x;      // 256 threads
    const int n   = t >> 2;
    const int j0  = (t & 3) * 4;      // uint index within row (uint = 2 bf16 along k)
#pragma unroll
    for (int jj = 0; jj < 4; jj++) {
        int j = j0 + jj;
        float v0 = W[(size_t)(kt * BK + 2 * j)     * T_DIM + n];
        float v1 = W[(size_t)(kt * BK + 2 * j + 1) * T_DIM + n];
        unsigned h = cvt_bf16x2(v0, v1);
        float r0 = v0 - lo_f32(h);
        float r1 = v1 - hi_f32(h);
        unsigned l = cvt_bf16x2(r0, r1);
        g_whi[kt * 1024 + n * 16 + j] = h;
        g_wlo[kt * 1024 + n * 16 + j] = l;
    }
}

// ---------------- fused GEMM (mma.sync bf16 3-term split) + loss ----------------
__global__ __launch_bounds__(THREADS, 1)
void fused_gemm_loss_kernel(const float* __restrict__ x,
                            const float* __restrict__ bias,
                            const int*   __restrict__ tagw,
                            const float* __restrict__ tts,
                            const int*   __restrict__ tptr)
{
    extern __shared__ char smem[];
    const uint32_t sb  = smem_u32(smem);
    const int tid  = threadIdx.x;
    const int wid  = tid >> 5;
    const int lane = tid & 31;
    const int wm   = wid >> 1;        // 0..7 (m group of 32 rows)
    const int wn   = wid & 1;         // 0..1 (n group of 32 cols)
    const int m0   = blockIdx.x * BM;

    if (tid < T_DIM) ((float*)(smem + SM_BIAS))[tid] = bias[tid];

    float c[2][4][4];
#pragma unroll
    for (int i = 0; i < 2; i++)
#pragma unroll
        for (int j = 0; j < 4; j++)
#pragma unroll
            for (int q = 0; q < 4; q++) c[i][j][q] = 0.0f;

    // ---- prefetch tile 0 ----
    float4 xv[4]; uint2 whv, wlv;
    {
#pragma unroll
        for (int i = 0; i < 4; i++) {
            int lin = i * THREADS + tid;         // 2048 float4 per tile
            int row = lin >> 3, c4 = lin & 7;
            xv[i] = *(const float4*)(x + (size_t)(m0 + row) * K_DIM + c4 * 4);
        }
        whv = ((const uint2*)g_whi)[tid];
        wlv = ((const uint2*)g_wlo)[tid];
    }

    // ---- store helper (lambda-free, inline) ----
    auto store_tile = [&](int b, const float4 xr[4], uint2 wh, uint2 wl) {
        char* ah = smem + A_HI_OFF + b * A_BUF;
        char* al = smem + A_LO_OFF + b * A_BUF;
#pragma unroll
        for (int i = 0; i < 4; i++) {
            int lin = i * THREADS + tid;
            int row = lin >> 3, c4 = lin & 7;
            float4 f = xr[i];
            unsigned h01 = cvt_bf16x2(f.x, f.y);
            unsigned h23 = cvt_bf16x2(f.z, f.w);
            float r0 = f.x - lo_f32(h01), r1 = f.y - hi_f32(h01);
            float r2 = f.z - lo_f32(h23), r3 = f.w - hi_f32(h23);
            unsigned l01 = cvt_bf16x2(r0, r1);
            unsigned l23 = cvt_bf16x2(r2, r3);
            *(uint2*)(ah + row * A_ROW + c4 * 8) = make_uint2(h01, h23);
            *(uint2*)(al + row * A_ROW + c4 * 8) = make_uint2(l01, l23);
        }
        int n = tid >> 3, j2 = (tid & 7) * 8;    // uint2 = 8 bytes
        *(uint2*)(smem + W_HI_OFF + b * W_BUF + n * A_ROW + j2) = wh;
        *(uint2*)(smem + W_LO_OFF + b * W_BUF + n * A_ROW + j2) = wl;
    };

    store_tile(0, xv, whv, wlv);
    __syncthreads();

    const int quad = lane >> 3, r8 = lane & 7;

    for (int kt = 0; kt < NTK; kt++) {
        const int b = kt & 1;

        // prefetch next tile (LDG early, hidden under MMA)
        if (kt + 1 < NTK) {
            const int k0 = (kt + 1) * BK;
#pragma unroll
            for (int i = 0; i < 4; i++) {
                int lin = i * THREADS + tid;
                int row = lin >> 3, c4 = lin & 7;
                xv[i] = *(const float4*)(x + (size_t)(m0 + row) * K_DIM + k0 + c4 * 4);
            }
            whv = ((const uint2*)g_whi)[(kt + 1) * 512 + tid];
            wlv = ((const uint2*)g_wlo)[(kt + 1) * 512 + tid];
        }

        // ---- compute on buffer b ----
        const uint32_t aH = sb + A_HI_OFF + b * A_BUF;
        const uint32_t aL = sb + A_LO_OFF + b * A_BUF;
        const uint32_t wH = sb + W_HI_OFF + b * W_BUF;
        const uint32_t wL = sb + W_LO_OFF + b * W_BUF;

#pragma unroll
        for (int kk = 0; kk < 2; kk++) {
            // B fragments: n32 x k16, tiles j=0..3 (regs [2j],[2j+1])
            unsigned bh[8], bl[8];
            const int nB = wn * 32 + ((quad >> 1) << 3) + r8;
            const int kB = kk * 16 + ((quad & 1) << 3);
#pragma unroll
            for (int s = 0; s < 2; s++) {
                uint32_t off = (uint32_t)(nB + s * 16) * A_ROW + kB * 2;
                LDMX4(&bh[s * 4], wH + off);
                LDMX4(&bl[s * 4], wL + off);
            }
            // A fragments per m16 tile, then 3-term MMAs
            const int kA = kk * 16 + ((quad >> 1) << 3);
#pragma unroll
            for (int i = 0; i < 2; i++) {
                unsigned ah[4], al[4];
                const int mA = wm * 32 + i * 16 + ((quad & 1) << 3) + r8;
                uint32_t off = (uint32_t)mA * A_ROW + kA * 2;
                LDMX4(ah, aH + off);
                LDMX4(al, aL + off);
#pragma unroll
                for (int j = 0; j < 4; j++) {
                    MMA16816(c[i][j], ah, bh[2 * j], bh[2 * j + 1]);
                    MMA16816(c[i][j], ah, bl[2 * j], bl[2 * j + 1]);
                    MMA16816(c[i][j], al, bh[2 * j], bh[2 * j + 1]);
                }
            }
        }

        if (kt + 1 < NTK) store_tile(b ^ 1, xv, whv, wlv);
        __syncthreads();
    }

    // ---- write C fragments to smem [256][65] f32 ----
    float* cs = (float*)(smem + A_HI_OFF);
    const int g = lane >> 2, tg = lane & 3;
#pragma unroll
    for (int i = 0; i < 2; i++)
#pragma unroll
        for (int j = 0; j < 4; j++) {
            int row = wm * 32 + i * 16 + g;
            int col = wn * 32 + j * 8 + tg * 2;
            cs[row * 65 + col]           = c[i][j][0];
            cs[row * 65 + col + 1]       = c[i][j][1];
            cs[(row + 8) * 65 + col]     = c[i][j][2];
            cs[(row + 8) * 65 + col + 1] = c[i][j][3];
        }
    __syncthreads();

    // ---- per-token loss/acc (threads 0..255) ----
    const float* biass = (const float*)(smem + SM_BIAS);
    float thr_loss = 0.0f; int thr_right = 0, thr_valid = 0;
    if (tid < BM) {
        const int token = m0 + tid;
        const int tag = (g_tag_stride == 2) ? tagw[2 * token] : tagw[token];
        const float* row = cs + tid * 65;

        float mv = -3.4e38f; int mi = 0;
        float sl = 0.0f, st = 0.0f;
#pragma unroll
        for (int cc = 0; cc < T_DIM; cc++) {
            float vv = row[cc] + biass[cc];
            sl += vv;
            if (vv > mv) { mv = vv; mi = cc; }
            if (cc == tag) st = vv;
        }
        float se = 0.0f;
#pragma unroll
        for (int cc = 0; cc < T_DIM; cc++)
            se += expf(row[cc] + biass[cc] - mv);

        const float E1 = 2.718281828459045f;
        float LSE = mv + logf(se);
        int   traw = *tptr;
        float tf = (traw > -1000000 && traw < 1000000) ? (float)traw : __int_as_float(traw);
        float s  = powf(tts[tag], tf);
        float es = expf(s);
        float Z  = 63.0f * E1 + es;
        thr_loss  = LSE - ((E1 / Z) * (sl - st) + (es / Z) * st);
        thr_valid = (tag < (T_DIM - 3)) ? 1 : 0;
        thr_right = (thr_valid && (mi == tag)) ? 1 : 0;
    }

    // ---- deterministic block reduction (16 warps) ----
    float* s_loss  = (float*)(smem + SM_REDF);
    int*   s_right = (int*)(smem + SM_REDR);
    int*   s_valid = (int*)(smem + SM_REDV);
#pragma unroll
    for (int off = 16; off > 0; off >>= 1) {
        thr_loss  += __shfl_xor_sync(0xffffffffu, thr_loss,  off);
        thr_right += __shfl_xor_sync(0xffffffffu, thr_right, off);
        thr_valid += __shfl_xor_sync(0xffffffffu, thr_valid, off);
    }
    if (lane == 0) { s_loss[wid] = thr_loss; s_right[wid] = thr_right; s_valid[wid] = thr_valid; }
    __syncthreads();
    if (tid == 0) {
        float L = 0.0f; int R = 0, V = 0;
        for (int w = 0; w < 16; w++) { L += s_loss[w]; R += s_right[w]; V += s_valid[w]; }
        g_part_loss[blockIdx.x]  = L;
        g_part_right[blockIdx.x] = R;
        g_part_valid[blockIdx.x] = V;
    }
}

// ---------------- final reduction ----------------
__global__ void finalize_kernel(float* __restrict__ out) {
    if (threadIdx.x == 0) {
        double L = 0.0; long long R = 0, V = 0;
        for (int i = 0; i < GRID; i++) {
            L += (double)g_part_loss[i];
            R += (long long)g_part_right[i];
            V += (long long)g_part_valid[i];
        }
        out[0] = (float)L;
        out[1] = (float)((double)R / (double)V);
    }
}

extern "C" void kernel_launch(void* const* d_in, const int* in_sizes, int n_in,
                              void* d_out, int out_size) {
    const float* x    = (const float*)d_in[0];
    const float* W    = (const float*)d_in[1];
    const float* b    = (const float*)d_in[2];
    const int*   tagw = (const int*)d_in[3];   // raw 32-bit view, dtype detected on device
    // d_in[4] = attention_mask: uniform additive shift over tag dim -> provably a no-op
    const float* tts  = (const float*)d_in[5];
    const int*   tptr = (const int*)d_in[6];

    static int smem_set = 0;
    if (!smem_set) {
        cudaFuncSetAttribute(fused_gemm_loss_kernel,
                             cudaFuncAttributeMaxDynamicSharedMemorySize, SMEM_TOTAL);
        smem_set = 1;
    }

    detect_tag_stride_kernel<<<1, 32>>>(tagw);
    w_convert_kernel<<<NTK, 256>>>(W);
    fused_gemm_loss_kernel<<<GRID, THREADS, SMEM_TOTAL>>>(x, b, tagw, tts, tptr);
    finalize_kernel<<<1, 32>>>((float*)d_out);
}

// round 5
// speedup vs baseline: 2.5190x; 1.1560x over previous
#include <cuda_runtime.h>
#include <cstdint>

// ---------------- problem constants ----------------
#define M_TOTAL 32768          // B*L tokens
#define K_DIM   1536           // H2
#define T_DIM   64             // tags
#define BM      256            // tokens per CTA
#define BK      32             // K per tile
#define NTK     (K_DIM / BK)   // 48 k-tiles
#define GRID    (M_TOTAL / BM) // 128 CTAs (one wave)
#define THREADS 512            // 16 warps: 8 (m) x 2 (n)

// ---------------- dynamic SMEM layout (bytes) ----------------
#define SM_REDF   128                    // 16 floats
#define SM_REDR   256                    // 16 ints
#define SM_REDV   320                    // 16 ints
#define SM_LAST   448                    // int flag
#define SM_BIAS   512                    // 64 floats
#define A_ROW     80
#define A_BUF     (BM * A_ROW)           // 20480
#define W_BUF     (T_DIM * A_ROW)        // 5120
#define A_HI_OFF  1024
#define A_LO_OFF  (A_HI_OFF + 2 * A_BUF) // 41984
#define W_HI_OFF  (A_LO_OFF + 2 * A_BUF) // 82944
#define W_LO_OFF  (W_HI_OFF + 2 * W_BUF) // 93184
#define SMEM_TOTAL (W_LO_OFF + 2 * W_BUF) // 103424
// C overlay (after GEMM): [256][65] f32 at offset 1024 = 66560 bytes (fits)

// ---------------- device scratch (no allocs allowed) ----------------
__device__ float    g_part_loss[GRID];
__device__ int      g_part_right[GRID];
__device__ int      g_part_valid[GRID];
__device__ int      g_tag_stride;
__device__ unsigned g_done;              // zero-init; last CTA resets to 0 each run
__device__ unsigned g_whi[NTK * 1024];   // W bf16 hi tiles, [kt][n=64][k=32] (uint = 2 bf16)
__device__ unsigned g_wlo[NTK * 1024];   // W bf16 lo tiles

// ---------------- helpers ----------------
__device__ __forceinline__ uint32_t smem_u32(const void* p) {
    uint32_t a;
    asm("{ .reg .u64 t; cvta.to.shared.u64 t, %1; cvt.u32.u64 %0, t; }" : "=r"(a) : "l"(p));
    return a;
}
__device__ __forceinline__ unsigned cvt_bf16x2(float a, float b) {
    // result: lo16 = bf16(a), hi16 = bf16(b)
    unsigned r;
    asm("cvt.rn.bf16x2.f32 %0, %1, %2;" : "=r"(r) : "f"(b), "f"(a));
    return r;
}
__device__ __forceinline__ float lo_f32(unsigned w) { return __uint_as_float(w << 16); }
__device__ __forceinline__ float hi_f32(unsigned w) { return __uint_as_float(w & 0xffff0000u); }

#define LDMX4(r, addr)                                                          \
    asm volatile("ldmatrix.sync.aligned.m8n8.x4.shared.b16 {%0,%1,%2,%3}, [%4];"\
                 : "=r"((r)[0]), "=r"((r)[1]), "=r"((r)[2]), "=r"((r)[3])       \
                 : "r"(addr))

#define MMA16816(c, a, b0, b1)                                                  \
    asm volatile("mma.sync.aligned.m16n8k16.row.col.f32.bf16.bf16.f32 "         \
                 "{%0,%1,%2,%3}, {%4,%5,%6,%7}, {%8,%9}, {%0,%1,%2,%3};"        \
                 : "+f"((c)[0]), "+f"((c)[1]), "+f"((c)[2]), "+f"((c)[3])       \
                 : "r"((a)[0]), "r"((a)[1]), "r"((a)[2]), "r"((a)[3]),          \
                   "r"(b0), "r"(b1))

// ---------------- prep: W -> bf16 hi/lo tiles + tag dtype detection ----------------
__global__ void prep_kernel(const float* __restrict__ W,
                            const int* __restrict__ tagw) {
    // parallel int32/int64 detection (block 0, warp 0): values < 64, so odd
    // words nonzero <=> tags are int32 pairs
    if (blockIdx.x == 0 && threadIdx.x < 32) {
        int l = threadIdx.x;
        int nz = 0;
#pragma unroll
        for (int i = 0; i < 4; i++) nz |= tagw[2 * (l + 32 * i) + 1];
        unsigned ball = __ballot_sync(0xffffffffu, nz != 0);
        if (l == 0) g_tag_stride = ball ? 1 : 2;
    }

    const int kt  = blockIdx.x;
    const int t   = threadIdx.x;      // 256 threads
    const int n   = t >> 2;
    const int j0  = (t & 3) * 4;      // uint index within row (uint = 2 bf16 along k)
#pragma unroll
    for (int jj = 0; jj < 4; jj++) {
        int j = j0 + jj;
        float v0 = W[(size_t)(kt * BK + 2 * j)     * T_DIM + n];
        float v1 = W[(size_t)(kt * BK + 2 * j + 1) * T_DIM + n];
        unsigned h = cvt_bf16x2(v0, v1);
        float r0 = v0 - lo_f32(h);
        float r1 = v1 - hi_f32(h);
        unsigned l = cvt_bf16x2(r0, r1);
        g_whi[kt * 1024 + n * 16 + j] = h;
        g_wlo[kt * 1024 + n * 16 + j] = l;
    }
}

// ---------------- fused GEMM (mma.sync bf16 3-term split) + loss + finalize ----------------
__global__ __launch_bounds__(THREADS, 1)
void fused_gemm_loss_kernel(const float* __restrict__ x,
                            const float* __restrict__ bias,
                            const int*   __restrict__ tagw,
                            const float* __restrict__ tts,
                            const int*   __restrict__ tptr,
                            float* __restrict__ out)
{
    extern __shared__ char smem[];
    const uint32_t sb  = smem_u32(smem);
    const int tid  = threadIdx.x;
    const int wid  = tid >> 5;
    const int lane = tid & 31;
    const int wm   = wid >> 1;        // 0..7 (m group of 32 rows)
    const int wn   = wid & 1;         // 0..1 (n group of 32 cols)
    const int m0   = blockIdx.x * BM;

    if (tid < T_DIM) ((float*)(smem + SM_BIAS))[tid] = bias[tid];

    float c[2][4][4];
#pragma unroll
    for (int i = 0; i < 2; i++)
#pragma unroll
        for (int j = 0; j < 4; j++)
#pragma unroll
            for (int q = 0; q < 4; q++) c[i][j][q] = 0.0f;

    // ---- prefetch tile 0 ----
    float4 xv[4]; uint2 whv, wlv;
    {
#pragma unroll
        for (int i = 0; i < 4; i++) {
            int lin = i * THREADS + tid;         // 2048 float4 per tile
            int row = lin >> 3, c4 = lin & 7;
            xv[i] = *(const float4*)(x + (size_t)(m0 + row) * K_DIM + c4 * 4);
        }
        whv = ((const uint2*)g_whi)[tid];
        wlv = ((const uint2*)g_wlo)[tid];
    }

    auto store_tile = [&](int b, const float4 xr[4], uint2 wh, uint2 wl) {
        char* ah = smem + A_HI_OFF + b * A_BUF;
        char* al = smem + A_LO_OFF + b * A_BUF;
#pragma unroll
        for (int i = 0; i < 4; i++) {
            int lin = i * THREADS + tid;
            int row = lin >> 3, c4 = lin & 7;
            float4 f = xr[i];
            unsigned h01 = cvt_bf16x2(f.x, f.y);
            unsigned h23 = cvt_bf16x2(f.z, f.w);
            float r0 = f.x - lo_f32(h01), r1 = f.y - hi_f32(h01);
            float r2 = f.z - lo_f32(h23), r3 = f.w - hi_f32(h23);
            unsigned l01 = cvt_bf16x2(r0, r1);
            unsigned l23 = cvt_bf16x2(r2, r3);
            *(uint2*)(ah + row * A_ROW + c4 * 8) = make_uint2(h01, h23);
            *(uint2*)(al + row * A_ROW + c4 * 8) = make_uint2(l01, l23);
        }
        int n = tid >> 3, j2 = (tid & 7) * 8;    // uint2 = 8 bytes
        *(uint2*)(smem + W_HI_OFF + b * W_BUF + n * A_ROW + j2) = wh;
        *(uint2*)(smem + W_LO_OFF + b * W_BUF + n * A_ROW + j2) = wl;
    };

    store_tile(0, xv, whv, wlv);
    __syncthreads();

    const int quad = lane >> 3, r8 = lane & 7;

    for (int kt = 0; kt < NTK; kt++) {
        const int b = kt & 1;

        // prefetch next tile (LDG early, hidden under MMA)
        if (kt + 1 < NTK) {
            const int k0 = (kt + 1) * BK;
#pragma unroll
            for (int i = 0; i < 4; i++) {
                int lin = i * THREADS + tid;
                int row = lin >> 3, c4 = lin & 7;
                xv[i] = *(const float4*)(x + (size_t)(m0 + row) * K_DIM + k0 + c4 * 4);
            }
            whv = ((const uint2*)g_whi)[(kt + 1) * 512 + tid];
            wlv = ((const uint2*)g_wlo)[(kt + 1) * 512 + tid];
        }

        // ---- compute on buffer b ----
        const uint32_t aH = sb + A_HI_OFF + b * A_BUF;
        const uint32_t aL = sb + A_LO_OFF + b * A_BUF;
        const uint32_t wH = sb + W_HI_OFF + b * W_BUF;
        const uint32_t wL = sb + W_LO_OFF + b * W_BUF;

#pragma unroll
        for (int kk = 0; kk < 2; kk++) {
            unsigned bh[8], bl[8];
            const int nB = wn * 32 + ((quad >> 1) << 3) + r8;
            const int kB = kk * 16 + ((quad & 1) << 3);
#pragma unroll
            for (int s = 0; s < 2; s++) {
                uint32_t off = (uint32_t)(nB + s * 16) * A_ROW + kB * 2;
                LDMX4(&bh[s * 4], wH + off);
                LDMX4(&bl[s * 4], wL + off);
            }
            const int kA = kk * 16 + ((quad >> 1) << 3);
#pragma unroll
            for (int i = 0; i < 2; i++) {
                unsigned ah[4], al[4];
                const int mA = wm * 32 + i * 16 + ((quad & 1) << 3) + r8;
                uint32_t off = (uint32_t)mA * A_ROW + kA * 2;
                LDMX4(ah, aH + off);
                LDMX4(al, aL + off);
#pragma unroll
                for (int j = 0; j < 4; j++) {
                    MMA16816(c[i][j], ah, bh[2 * j], bh[2 * j + 1]);
                    MMA16816(c[i][j], ah, bl[2 * j], bl[2 * j + 1]);
                    MMA16816(c[i][j], al, bh[2 * j], bh[2 * j + 1]);
                }
            }
        }

        if (kt + 1 < NTK) store_tile(b ^ 1, xv, whv, wlv);
        __syncthreads();
    }

    // ---- write C fragments to smem [256][65] f32 ----
    float* cs = (float*)(smem + A_HI_OFF);
    const int g = lane >> 2, tg = lane & 3;
#pragma unroll
    for (int i = 0; i < 2; i++)
#pragma unroll
        for (int j = 0; j < 4; j++) {
            int row = wm * 32 + i * 16 + g;
            int col = wn * 32 + j * 8 + tg * 2;
            cs[row * 65 + col]           = c[i][j][0];
            cs[row * 65 + col + 1]       = c[i][j][1];
            cs[(row + 8) * 65 + col]     = c[i][j][2];
            cs[(row + 8) * 65 + col + 1] = c[i][j][3];
        }
    __syncthreads();

    // ---- per-token loss/acc (threads 0..255) ----
    const float* biass = (const float*)(smem + SM_BIAS);
    float thr_loss = 0.0f; int thr_right = 0, thr_valid = 0;
    if (tid < BM) {
        const int token = m0 + tid;
        const int tag = (g_tag_stride == 2) ? tagw[2 * token] : tagw[token];
        const float* row = cs + tid * 65;

        float mv = -3.4e38f; int mi = 0;
        float sl = 0.0f, st = 0.0f;
#pragma unroll
        for (int cc = 0; cc < T_DIM; cc++) {
            float vv = row[cc] + biass[cc];
            sl += vv;
            if (vv > mv) { mv = vv; mi = cc; }
            if (cc == tag) st = vv;
        }
        float se = 0.0f;
#pragma unroll
        for (int cc = 0; cc < T_DIM; cc++)
            se += expf(row[cc] + biass[cc] - mv);

        const float E1 = 2.718281828459045f;
        float LSE = mv + logf(se);
        int   traw = *tptr;
        float tf = (traw > -1000000 && traw < 1000000) ? (float)traw : __int_as_float(traw);
        float s  = powf(tts[tag], tf);
        float es = expf(s);
        float Z  = 63.0f * E1 + es;
        thr_loss  = LSE - ((E1 / Z) * (sl - st) + (es / Z) * st);
        thr_valid = (tag < (T_DIM - 3)) ? 1 : 0;
        thr_right = (thr_valid && (mi == tag)) ? 1 : 0;
    }

    // ---- deterministic block reduction (16 warps) ----
    float* s_loss  = (float*)(smem + SM_REDF);
    int*   s_right = (int*)(smem + SM_REDR);
    int*   s_valid = (int*)(smem + SM_REDV);
    int*   s_last  = (int*)(smem + SM_LAST);
#pragma unroll
    for (int off = 16; off > 0; off >>= 1) {
        thr_loss  += __shfl_xor_sync(0xffffffffu, thr_loss,  off);
        thr_right += __shfl_xor_sync(0xffffffffu, thr_right, off);
        thr_valid += __shfl_xor_sync(0xffffffffu, thr_valid, off);
    }
    if (lane == 0) { s_loss[wid] = thr_loss; s_right[wid] = thr_right; s_valid[wid] = thr_valid; }
    __syncthreads();
    if (tid == 0) {
        float L = 0.0f; int R = 0, V = 0;
        for (int w = 0; w < 16; w++) { L += s_loss[w]; R += s_right[w]; V += s_valid[w]; }
        g_part_loss[blockIdx.x]  = L;
        g_part_right[blockIdx.x] = R;
        g_part_valid[blockIdx.x] = V;
        __threadfence();
        unsigned prev = atomicAdd(&g_done, 1u);
        *s_last = (prev == GRID - 1) ? 1 : 0;
    }
    __syncthreads();

    // ---- last CTA: deterministic global reduction + output ----
    if (*s_last) {
        __threadfence();   // acquire all partials
        float L = 0.0f; int R = 0, V = 0;
        if (tid < GRID) {  // GRID == 128 -> warps 0..3
            L = g_part_loss[tid];
            R = g_part_right[tid];
            V = g_part_valid[tid];
        }
        if (tid < 128) {
#pragma unroll
            for (int off = 16; off > 0; off >>= 1) {
                L += __shfl_xor_sync(0xffffffffu, L, off);
                R += __shfl_xor_sync(0xffffffffu, R, off);
                V += __shfl_xor_sync(0xffffffffu, V, off);
            }
            if (lane == 0) { s_loss[wid] = L; s_right[wid] = R; s_valid[wid] = V; }
        }
        __syncthreads();
        if (tid == 0) {
            double LT = 0.0; long long RT = 0, VT = 0;
            for (int w = 0; w < 4; w++) {
                LT += (double)s_loss[w]; RT += s_right[w]; VT += s_valid[w];
            }
            out[0] = (float)LT;
            out[1] = (float)((double)RT / (double)VT);
            atomicExch(&g_done, 0u);   // reset for next graph replay
        }
    }
}

extern "C" void kernel_launch(void* const* d_in, const int* in_sizes, int n_in,
                              void* d_out, int out_size) {
    const float* x    = (const float*)d_in[0];
    const float* W    = (const float*)d_in[1];
    const float* b    = (const float*)d_in[2];
    const int*   tagw = (const int*)d_in[3];   // raw 32-bit view, dtype detected on device
    // d_in[4] = attention_mask: uniform additive shift over tag dim -> provably a no-op
    const float* tts  = (const float*)d_in[5];
    const int*   tptr = (const int*)d_in[6];

    static int smem_set = 0;
    if (!smem_set) {
        cudaFuncSetAttribute(fused_gemm_loss_kernel,
                             cudaFuncAttributeMaxDynamicSharedMemorySize, SMEM_TOTAL);
        smem_set = 1;
    }

    prep_kernel<<<NTK, 256>>>(W, tagw);
    fused_gemm_loss_kernel<<<GRID, THREADS, SMEM_TOTAL>>>(x, b, tagw, tts, tptr,
                                                          (float*)d_out);
}

// round 6
// speedup vs baseline: 2.5275x; 1.0034x over previous
#include <cuda_runtime.h>
#include <cstdint>

// ---------------- problem constants ----------------
#define M_TOTAL 32768          // B*L tokens
#define K_DIM   1536           // H2
#define T_DIM   64             // tags
#define BM      128            // tokens per CTA
#define BK      32             // K per tile
#define NTK     (K_DIM / BK)   // 48 k-tiles
#define GRID    (M_TOTAL / BM) // 256 CTAs (~2 per SM)
#define THREADS 256            // 8 warps: 4 (m) x 2 (n)

// ---------------- dynamic SMEM layout (bytes) ----------------
#define SM_REDF   128                    // 8 floats
#define SM_REDR   192                    // 8 ints
#define SM_REDV   256                    // 8 ints
#define SM_LAST   448                    // int flag
#define SM_BIAS   512                    // 64 floats
#define A_ROW     80
#define A_BUF     (BM * A_ROW)           // 10240
#define W_BUF     (T_DIM * A_ROW)        // 5120
#define A_HI_OFF  1024
#define A_LO_OFF  (A_HI_OFF + 2 * A_BUF) // 21504
#define W_HI_OFF  (A_LO_OFF + 2 * A_BUF) // 41984
#define W_LO_OFF  (W_HI_OFF + 2 * W_BUF) // 52224
#define SMEM_TOTAL (W_LO_OFF + 2 * W_BUF) // 62464  -> 2 CTAs/SM
// C overlay (after GEMM): [128][65] f32 at offset 1024 = 33280 bytes (fits)

// ---------------- device scratch (no allocs allowed) ----------------
__device__ float    g_part_loss[GRID];
__device__ int      g_part_right[GRID];
__device__ int      g_part_valid[GRID];
__device__ int      g_tag_stride;
__device__ unsigned g_done;              // zero-init; last CTA resets to 0 each run
__device__ unsigned g_whi[NTK * 1024];   // W bf16 hi tiles, [kt][n=64][k=32] (uint = 2 bf16)
__device__ unsigned g_wlo[NTK * 1024];   // W bf16 lo tiles

// ---------------- helpers ----------------
__device__ __forceinline__ uint32_t smem_u32(const void* p) {
    uint32_t a;
    asm("{ .reg .u64 t; cvta.to.shared.u64 t, %1; cvt.u32.u64 %0, t; }" : "=r"(a) : "l"(p));
    return a;
}
__device__ __forceinline__ unsigned cvt_bf16x2(float a, float b) {
    // result: lo16 = bf16(a), hi16 = bf16(b)
    unsigned r;
    asm("cvt.rn.bf16x2.f32 %0, %1, %2;" : "=r"(r) : "f"(b), "f"(a));
    return r;
}
__device__ __forceinline__ float lo_f32(unsigned w) { return __uint_as_float(w << 16); }
__device__ __forceinline__ float hi_f32(unsigned w) { return __uint_as_float(w & 0xffff0000u); }

#define LDMX4(r, addr)                                                          \
    asm volatile("ldmatrix.sync.aligned.m8n8.x4.shared.b16 {%0,%1,%2,%3}, [%4];"\
                 : "=r"((r)[0]), "=r"((r)[1]), "=r"((r)[2]), "=r"((r)[3])       \
                 : "r"(addr))

#define MMA16816(c, a, b0, b1)                                                  \
    asm volatile("mma.sync.aligned.m16n8k16.row.col.f32.bf16.bf16.f32 "         \
                 "{%0,%1,%2,%3}, {%4,%5,%6,%7}, {%8,%9}, {%0,%1,%2,%3};"        \
                 : "+f"((c)[0]), "+f"((c)[1]), "+f"((c)[2]), "+f"((c)[3])       \
                 : "r"((a)[0]), "r"((a)[1]), "r"((a)[2]), "r"((a)[3]),          \
                   "r"(b0), "r"(b1))

// ---------------- prep: W -> bf16 hi/lo tiles + tag dtype detection ----------------
__global__ void prep_kernel(const float* __restrict__ W,
                            const int* __restrict__ tagw) {
    if (blockIdx.x == 0 && threadIdx.x < 32) {
        int l = threadIdx.x;
        int nz = 0;
#pragma unroll
        for (int i = 0; i < 4; i++) nz |= tagw[2 * (l + 32 * i) + 1];
        unsigned ball = __ballot_sync(0xffffffffu, nz != 0);
        if (l == 0) g_tag_stride = ball ? 1 : 2;
    }

    const int kt  = blockIdx.x;
    const int t   = threadIdx.x;      // 256 threads
    const int n   = t >> 2;
    const int j0  = (t & 3) * 4;      // uint index within row (uint = 2 bf16 along k)
#pragma unroll
    for (int jj = 0; jj < 4; jj++) {
        int j = j0 + jj;
        float v0 = W[(size_t)(kt * BK + 2 * j)     * T_DIM + n];
        float v1 = W[(size_t)(kt * BK + 2 * j + 1) * T_DIM + n];
        unsigned h = cvt_bf16x2(v0, v1);
        float r0 = v0 - lo_f32(h);
        float r1 = v1 - hi_f32(h);
        unsigned l = cvt_bf16x2(r0, r1);
        g_whi[kt * 1024 + n * 16 + j] = h;
        g_wlo[kt * 1024 + n * 16 + j] = l;
    }
}

// ---------------- fused GEMM (mma.sync bf16 3-term split) + loss + finalize ----------------
__global__ __launch_bounds__(THREADS, 2)
void fused_gemm_loss_kernel(const float* __restrict__ x,
                            const float* __restrict__ bias,
                            const int*   __restrict__ tagw,
                            const float* __restrict__ tts,
                            const int*   __restrict__ tptr,
                            float* __restrict__ out)
{
    extern __shared__ char smem[];
    const uint32_t sb  = smem_u32(smem);
    const int tid  = threadIdx.x;
    const int wid  = tid >> 5;
    const int lane = tid & 31;
    const int wm   = wid >> 1;        // 0..3 (m group of 32 rows)
    const int wn   = wid & 1;         // 0..1 (n group of 32 cols)
    const int m0   = blockIdx.x * BM;

    if (tid < T_DIM) ((float*)(smem + SM_BIAS))[tid] = bias[tid];

    float c[2][4][4];
#pragma unroll
    for (int i = 0; i < 2; i++)
#pragma unroll
        for (int j = 0; j < 4; j++)
#pragma unroll
            for (int q = 0; q < 4; q++) c[i][j][q] = 0.0f;

    // ---- prefetch tile 0 ----
    // x tile: 128 rows x 32 floats = 1024 float4; 256 threads -> 4 each
    // W tile: 512 uint2; 256 threads -> 2 each
    float4 xv[4]; uint2 whv[2], wlv[2];
    {
#pragma unroll
        for (int i = 0; i < 4; i++) {
            int lin = i * THREADS + tid;
            int row = lin >> 3, c4 = lin & 7;
            xv[i] = *(const float4*)(x + (size_t)(m0 + row) * K_DIM + c4 * 4);
        }
        whv[0] = ((const uint2*)g_whi)[tid];
        whv[1] = ((const uint2*)g_whi)[tid + 256];
        wlv[0] = ((const uint2*)g_wlo)[tid];
        wlv[1] = ((const uint2*)g_wlo)[tid + 256];
    }

    auto store_tile = [&](int b, const float4 xr[4], const uint2 wh[2], const uint2 wl[2]) {
        char* ah = smem + A_HI_OFF + b * A_BUF;
        char* al = smem + A_LO_OFF + b * A_BUF;
#pragma unroll
        for (int i = 0; i < 4; i++) {
            int lin = i * THREADS + tid;
            int row = lin >> 3, c4 = lin & 7;
            float4 f = xr[i];
            unsigned h01 = cvt_bf16x2(f.x, f.y);
            unsigned h23 = cvt_bf16x2(f.z, f.w);
            float r0 = f.x - lo_f32(h01), r1 = f.y - hi_f32(h01);
            float r2 = f.z - lo_f32(h23), r3 = f.w - hi_f32(h23);
            unsigned l01 = cvt_bf16x2(r0, r1);
            unsigned l23 = cvt_bf16x2(r2, r3);
            *(uint2*)(ah + row * A_ROW + c4 * 8) = make_uint2(h01, h23);
            *(uint2*)(al + row * A_ROW + c4 * 8) = make_uint2(l01, l23);
        }
#pragma unroll
        for (int i = 0; i < 2; i++) {
            int idx = i * THREADS + tid;
            int n = idx >> 3, j2 = (idx & 7) * 8;  // uint2 = 8 bytes
            *(uint2*)(smem + W_HI_OFF + b * W_BUF + n * A_ROW + j2) = wh[i];
            *(uint2*)(smem + W_LO_OFF + b * W_BUF + n * A_ROW + j2) = wl[i];
        }
    };

    store_tile(0, xv, whv, wlv);
    __syncthreads();

    const int quad = lane >> 3, r8 = lane & 7;

    for (int kt = 0; kt < NTK; kt++) {
        const int b = kt & 1;

        // prefetch next tile (LDG early, hidden under MMA)
        if (kt + 1 < NTK) {
            const int k0 = (kt + 1) * BK;
#pragma unroll
            for (int i = 0; i < 4; i++) {
                int lin = i * THREADS + tid;
                int row = lin >> 3, c4 = lin & 7;
                xv[i] = *(const float4*)(x + (size_t)(m0 + row) * K_DIM + k0 + c4 * 4);
            }
            whv[0] = ((const uint2*)g_whi)[(kt + 1) * 512 + tid];
            whv[1] = ((const uint2*)g_whi)[(kt + 1) * 512 + tid + 256];
            wlv[0] = ((const uint2*)g_wlo)[(kt + 1) * 512 + tid];
            wlv[1] = ((const uint2*)g_wlo)[(kt + 1) * 512 + tid + 256];
        }

        // ---- compute on buffer b ----
        const uint32_t aH = sb + A_HI_OFF + b * A_BUF;
        const uint32_t aL = sb + A_LO_OFF + b * A_BUF;
        const uint32_t wH = sb + W_HI_OFF + b * W_BUF;
        const uint32_t wL = sb + W_LO_OFF + b * W_BUF;

#pragma unroll
        for (int kk = 0; kk < 2; kk++) {
            unsigned bh[8], bl[8];
            const int nB = wn * 32 + ((quad >> 1) << 3) + r8;
            const int kB = kk * 16 + ((quad & 1) << 3);
#pragma unroll
            for (int s = 0; s < 2; s++) {
                uint32_t off = (uint32_t)(nB + s * 16) * A_ROW + kB * 2;
                LDMX4(&bh[s * 4], wH + off);
                LDMX4(&bl[s * 4], wL + off);
            }
            const int kA = kk * 16 + ((quad >> 1) << 3);
#pragma unroll
            for (int i = 0; i < 2; i++) {
                unsigned ah[4], al[4];
                const int mA = wm * 32 + i * 16 + ((quad & 1) << 3) + r8;
                uint32_t off = (uint32_t)mA * A_ROW + kA * 2;
                LDMX4(ah, aH + off);
                LDMX4(al, aL + off);
#pragma unroll
                for (int j = 0; j < 4; j++) {
                    MMA16816(c[i][j], ah, bh[2 * j], bh[2 * j + 1]);
                    MMA16816(c[i][j], ah, bl[2 * j], bl[2 * j + 1]);
                    MMA16816(c[i][j], al, bh[2 * j], bh[2 * j + 1]);
                }
            }
        }

        if (kt + 1 < NTK) store_tile(b ^ 1, xv, whv, wlv);
        __syncthreads();
    }

    // ---- write C fragments to smem [128][65] f32 ----
    float* cs = (float*)(smem + A_HI_OFF);
    const int g = lane >> 2, tg = lane & 3;
#pragma unroll
    for (int i = 0; i < 2; i++)
#pragma unroll
        for (int j = 0; j < 4; j++) {
            int row = wm * 32 + i * 16 + g;
            int col = wn * 32 + j * 8 + tg * 2;
            cs[row * 65 + col]           = c[i][j][0];
            cs[row * 65 + col + 1]       = c[i][j][1];
            cs[(row + 8) * 65 + col]     = c[i][j][2];
            cs[(row + 8) * 65 + col + 1] = c[i][j][3];
        }
    __syncthreads();

    // ---- per-token loss/acc (threads 0..127) ----
    const float* biass = (const float*)(smem + SM_BIAS);
    float thr_loss = 0.0f; int thr_right = 0, thr_valid = 0;
    if (tid < BM) {
        const int token = m0 + tid;
        const int tag = (g_tag_stride == 2) ? tagw[2 * token] : tagw[token];
        const float* row = cs + tid * 65;

        float mv = -3.4e38f; int mi = 0;
        float sl = 0.0f, st = 0.0f;
#pragma unroll
        for (int cc = 0; cc < T_DIM; cc++) {
            float vv = row[cc] + biass[cc];
            sl += vv;
            if (vv > mv) { mv = vv; mi = cc; }
            if (cc == tag) st = vv;
        }
        float se = 0.0f;
#pragma unroll
        for (int cc = 0; cc < T_DIM; cc++)
            se += expf(row[cc] + biass[cc] - mv);

        const float E1 = 2.718281828459045f;
        float LSE = mv + logf(se);
        int   traw = *tptr;
        float tf = (traw > -1000000 && traw < 1000000) ? (float)traw : __int_as_float(traw);
        float s  = powf(tts[tag], tf);
        float es = expf(s);
        float Z  = 63.0f * E1 + es;
        thr_loss  = LSE - ((E1 / Z) * (sl - st) + (es / Z) * st);
        thr_valid = (tag < (T_DIM - 3)) ? 1 : 0;
        thr_right = (thr_valid && (mi == tag)) ? 1 : 0;
    }

    // ---- deterministic block reduction (8 warps) ----
    float* s_loss  = (float*)(smem + SM_REDF);
    int*   s_right = (int*)(smem + SM_REDR);
    int*   s_valid = (int*)(smem + SM_REDV);
    int*   s_last  = (int*)(smem + SM_LAST);
#pragma unroll
    for (int off = 16; off > 0; off >>= 1) {
        thr_loss  += __shfl_xor_sync(0xffffffffu, thr_loss,  off);
        thr_right += __shfl_xor_sync(0xffffffffu, thr_right, off);
        thr_valid += __shfl_xor_sync(0xffffffffu, thr_valid, off);
    }
    if (lane == 0) { s_loss[wid] = thr_loss; s_right[wid] = thr_right; s_valid[wid] = thr_valid; }
    __syncthreads();
    if (tid == 0) {
        float L = 0.0f; int R = 0, V = 0;
        for (int w = 0; w < 8; w++) { L += s_loss[w]; R += s_right[w]; V += s_valid[w]; }
        g_part_loss[blockIdx.x]  = L;
        g_part_right[blockIdx.x] = R;
        g_part_valid[blockIdx.x] = V;
        __threadfence();
        unsigned prev = atomicAdd(&g_done, 1u);
        *s_last = (prev == GRID - 1) ? 1 : 0;
    }
    __syncthreads();

    // ---- last CTA: deterministic global reduction + output ----
    if (*s_last) {
        __threadfence();   // acquire all partials
        float L = g_part_loss[tid];        // GRID == 256 == THREADS
        int   R = g_part_right[tid];
        int   V = g_part_valid[tid];
#pragma unroll
        for (int off = 16; off > 0; off >>= 1) {
            L += __shfl_xor_sync(0xffffffffu, L, off);
            R += __shfl_xor_sync(0xffffffffu, R, off);
            V += __shfl_xor_sync(0xffffffffu, V, off);
        }
        if (lane == 0) { s_loss[wid] = L; s_right[wid] = R; s_valid[wid] = V; }
        __syncthreads();
        if (tid == 0) {
            double LT = 0.0; long long RT = 0, VT = 0;
            for (int w = 0; w < 8; w++) {
                LT += (double)s_loss[w]; RT += s_right[w]; VT += s_valid[w];
            }
            out[0] = (float)LT;
            out[1] = (float)((double)RT / (double)VT);
            atomicExch(&g_done, 0u);   // reset for next graph replay
        }
    }
}

extern "C" void kernel_launch(void* const* d_in, const int* in_sizes, int n_in,
                              void* d_out, int out_size) {
    const float* x    = (const float*)d_in[0];
    const float* W    = (const float*)d_in[1];
    const float* b    = (const float*)d_in[2];
    const int*   tagw = (const int*)d_in[3];   // raw 32-bit view, dtype detected on device
    // d_in[4] = attention_mask: uniform additive shift over tag dim -> provably a no-op
    const float* tts  = (const float*)d_in[5];
    const int*   tptr = (const int*)d_in[6];

    static int smem_set = 0;
    if (!smem_set) {
        cudaFuncSetAttribute(fused_gemm_loss_kernel,
                             cudaFuncAttributeMaxDynamicSharedMemorySize, SMEM_TOTAL);
        smem_set = 1;
    }

    prep_kernel<<<NTK, 256>>>(W, tagw);
    fused_gemm_loss_kernel<<<GRID, THREADS, SMEM_TOTAL>>>(x, b, tagw, tts, tptr,
                                                          (float*)d_out);
}